// round 2
// baseline (speedup 1.0000x reference)
#include <cuda_runtime.h>
#include <cuda_bf16.h>
#include <math.h>

#define NLAYER 6
#define DV     512      // d_model
#define NH     8
#define HD     64
#define DFF    2048
#define BB     8
#define LL     1024
#define MM     (BB*LL)  // 8192 rows
#define QKV_STRIDE (3*DV)

// ---------------- scratch (static device globals; no allocation) ----------------
__device__ float g_out [MM*DV];
__device__ float g_qkv [MM*3*DV];
__device__ float g_attn[MM*DV];
__device__ float g_tmp [MM*DV];
__device__ float g_h   [MM*DFF];
__device__ unsigned char g_kpm[MM];

// ---------------- key padding mask: kpm[b,l] = all(x[b,l,:] == 0) ----------------
__global__ void kpm_kernel(const float* __restrict__ x, unsigned char* __restrict__ kpm)
{
    int row = blockIdx.x;
    int t = threadIdx.x;
    int nz = 0;
    for (int c = t; c < DV; c += 128)
        nz |= (x[(size_t)row * DV + c] != 0.0f) ? 1 : 0;
    nz = __syncthreads_or(nz);
    if (t == 0) kpm[row] = nz ? 0 : 1;
}

// ---------------- float4 copy ----------------
__global__ void copy_kernel(const float* __restrict__ src, float* __restrict__ dst, int n4)
{
    int i = blockIdx.x * blockDim.x + threadIdx.x;
    if (i < n4) ((float4*)dst)[i] = ((const float4*)src)[i];
}

// ---------------- SIMT fp32 GEMM: C[m,n] = sum_k A[m,k] * W[n,k] + bias[n] ----------------
// A: M x K row-major, W: N x K row-major (PyTorch Linear layout), C: M x N
// 128x128 tile, 256 threads, 8x8 per thread, K-tile 16. All dims divisible.
template<bool GELU>
__global__ __launch_bounds__(256) void gemm_kernel(
    const float* __restrict__ A, const float* __restrict__ W,
    const float* __restrict__ bias, float* __restrict__ C,
    int M, int N, int K)
{
    __shared__ float As[16][128];
    __shared__ float Bs[16][128];
    const int bm = blockIdx.y * 128;
    const int bn = blockIdx.x * 128;
    const int t  = threadIdx.x;
    const int tm = (t >> 4) * 8;       // 0..120
    const int tn = (t & 15) * 8;       // 0..120

    float acc[8][8];
#pragma unroll
    for (int i = 0; i < 8; i++)
#pragma unroll
        for (int j = 0; j < 8; j++) acc[i][j] = 0.0f;

    for (int k0 = 0; k0 < K; k0 += 16) {
#pragma unroll
        for (int r = 0; r < 2; r++) {
            int idx = t + r * 256;            // 0..511 float4 slots
            int row = idx >> 2;               // 0..127
            int kv  = (idx & 3) << 2;         // 0,4,8,12
            float4 a4 = *(const float4*)(A + (size_t)(bm + row) * K + k0 + kv);
            As[kv+0][row] = a4.x; As[kv+1][row] = a4.y;
            As[kv+2][row] = a4.z; As[kv+3][row] = a4.w;
            float4 w4 = *(const float4*)(W + (size_t)(bn + row) * K + k0 + kv);
            Bs[kv+0][row] = w4.x; Bs[kv+1][row] = w4.y;
            Bs[kv+2][row] = w4.z; Bs[kv+3][row] = w4.w;
        }
        __syncthreads();
#pragma unroll
        for (int k = 0; k < 16; k++) {
            float a[8], b[8];
            *(float4*)&a[0] = *(const float4*)&As[k][tm];
            *(float4*)&a[4] = *(const float4*)&As[k][tm + 4];
            *(float4*)&b[0] = *(const float4*)&Bs[k][tn];
            *(float4*)&b[4] = *(const float4*)&Bs[k][tn + 4];
#pragma unroll
            for (int i = 0; i < 8; i++)
#pragma unroll
                for (int j = 0; j < 8; j++)
                    acc[i][j] = fmaf(a[i], b[j], acc[i][j]);
        }
        __syncthreads();
    }

    float bb[8];
#pragma unroll
    for (int j = 0; j < 8; j++) bb[j] = bias[bn + tn + j];

#pragma unroll
    for (int i = 0; i < 8; i++) {
        size_t row = (size_t)(bm + tm + i);
        float r[8];
#pragma unroll
        for (int j = 0; j < 8; j++) {
            float v = acc[i][j] + bb[j];
            if (GELU) v = 0.5f * v * (1.0f + erff(v * 0.70710678118654752f));
            r[j] = v;
        }
        *(float4*)(C + row * N + bn + tn)     = make_float4(r[0], r[1], r[2], r[3]);
        *(float4*)(C + row * N + bn + tn + 4) = make_float4(r[4], r[5], r[6], r[7]);
    }
}

// ---------------- flash-style causal attention with relative-position bias ----------------
// grid: (B*H, L/128); 128 threads; thread t owns query i = qbase + t.
// qkv layout: [B*L, 3*DV]; q at col h*HD, k at DV + h*HD, v at 2*DV + h*HD.
#define KT 8
__global__ __launch_bounds__(128) void attn_kernel(
    const float* __restrict__ qkv, const float* __restrict__ dist_emb,
    const unsigned char* __restrict__ kpm, float* __restrict__ outp)
{
    __shared__ float sK[KT][HD];
    __shared__ float sV[KT][HD];
    __shared__ float sb[LL];             // bias column for this head: sb[d] = dist_emb[d][h]
    __shared__ unsigned char skpm[LL];   // key padding for this batch

    const int bh = blockIdx.x;
    const int b = bh / NH, h = bh % NH;
    const int qbase = blockIdx.y * 128;
    const int t = threadIdx.x;
    const int i = qbase + t;

    for (int d = t; d < LL; d += 128) {
        sb[d] = dist_emb[d * NH + h];
        skpm[d] = kpm[b * LL + d];
    }

    float q[HD];
    const float* qptr = qkv + (size_t)(b * LL + i) * QKV_STRIDE + h * HD;
#pragma unroll
    for (int d = 0; d < HD; d += 4) {
        float4 v4 = *(const float4*)(qptr + d);
        q[d] = v4.x; q[d+1] = v4.y; q[d+2] = v4.z; q[d+3] = v4.w;
    }

    float m = -1e30f, lsum = 0.0f;
    float acc[HD];
#pragma unroll
    for (int d = 0; d < HD; d++) acc[d] = 0.0f;

    __syncthreads();   // sb / skpm ready

    const float scale = 0.125f;   // 1/sqrt(64)
    const int jend = qbase + 128; // max key index (exclusive) in this block

    for (int jt = 0; jt < jend; jt += KT) {
        // cooperative load K/V tile: KT*HD = 512 floats each, 1 float4 per thread per array
        {
            int krow = t >> 4;           // 0..7
            int kc   = (t & 15) * 4;     // 0..60
            const float* kp = qkv + (size_t)(b * LL + jt + krow) * QKV_STRIDE + DV   + h * HD + kc;
            const float* vp = qkv + (size_t)(b * LL + jt + krow) * QKV_STRIDE + 2*DV + h * HD + kc;
            *(float4*)&sK[krow][kc] = *(const float4*)kp;
            *(float4*)&sV[krow][kc] = *(const float4*)vp;
        }
        __syncthreads();

        float s[KT];
#pragma unroll
        for (int jj = 0; jj < KT; jj++) {
            int j = jt + jj;
            float dotv = 0.0f;
#pragma unroll
            for (int d = 0; d < HD; d++) dotv = fmaf(q[d], sK[jj][d], dotv);
            float sc = -1e30f;
            if (j <= i && !skpm[j]) {
                sc = dotv * scale + sb[i - j];
            }
            s[jj] = sc;
        }
        float tmax = s[0];
#pragma unroll
        for (int jj = 1; jj < KT; jj++) tmax = fmaxf(tmax, s[jj]);
        float mnew = fmaxf(m, tmax);
        float alpha = (m > -1e29f) ? __expf(m - mnew) : 0.0f;
        lsum *= alpha;
#pragma unroll
        for (int d = 0; d < HD; d++) acc[d] *= alpha;
#pragma unroll
        for (int jj = 0; jj < KT; jj++) {
            float p = (s[jj] > -1e29f) ? __expf(s[jj] - mnew) : 0.0f;
            lsum += p;
#pragma unroll
            for (int d = 0; d < HD; d++) acc[d] = fmaf(p, sV[jj][d], acc[d]);
        }
        m = mnew;
        __syncthreads();
    }

    float inv = 1.0f / lsum;
    float* op = outp + (size_t)(b * LL + i) * DV + h * HD;
#pragma unroll
    for (int d = 0; d < HD; d += 4)
        *(float4*)(op + d) = make_float4(acc[d]*inv, acc[d+1]*inv, acc[d+2]*inv, acc[d+3]*inv);
}

// ---------------- residual + LayerNorm: out = LN(x + res) * g + beta ----------------
__global__ __launch_bounds__(128) void ln_kernel(
    const float* __restrict__ x, const float* __restrict__ res,
    const float* __restrict__ g, const float* __restrict__ beta,
    float* __restrict__ outp)
{
    const int row = blockIdx.x;
    const int t = threadIdx.x;
    const float* xr = x + (size_t)row * DV;

    float v[4];
#pragma unroll
    for (int k = 0; k < 4; k++) {
        int c = k * 128 + t;
        float val = xr[c];
        if (res) val += res[(size_t)row * DV + c];
        v[k] = val;
    }
    float s = 0.0f, ss = 0.0f;
#pragma unroll
    for (int k = 0; k < 4; k++) { s += v[k]; ss += v[k] * v[k]; }
#pragma unroll
    for (int o = 16; o > 0; o >>= 1) {
        s  += __shfl_xor_sync(0xFFFFFFFFu, s,  o);
        ss += __shfl_xor_sync(0xFFFFFFFFu, ss, o);
    }
    __shared__ float rs[4], rss[4];
    int w = t >> 5;
    if ((t & 31) == 0) { rs[w] = s; rss[w] = ss; }
    __syncthreads();
    s  = rs[0] + rs[1] + rs[2] + rs[3];
    ss = rss[0] + rss[1] + rss[2] + rss[3];
    float mean = s * (1.0f / DV);
    float var  = ss * (1.0f / DV) - mean * mean;
    float r = rsqrtf(var + 1e-5f);
#pragma unroll
    for (int k = 0; k < 4; k++) {
        int c = k * 128 + t;
        outp[(size_t)row * DV + c] = (v[k] - mean) * r * g[c] + beta[c];
    }
}

// ---------------- host launcher ----------------
extern "C" void kernel_launch(void* const* d_in, const int* in_sizes, int n_in,
                              void* d_out, int out_size)
{
    (void)in_sizes; (void)n_in; (void)out_size;
    const float* x         = (const float*)d_in[0];
    const float* dist_emb  = (const float*)d_in[1];
    const float* in_proj_w = (const float*)d_in[2];
    const float* in_proj_b = (const float*)d_in[3];
    const float* out_w     = (const float*)d_in[4];
    const float* out_b     = (const float*)d_in[5];
    const float* lin1_w    = (const float*)d_in[6];
    const float* lin1_b    = (const float*)d_in[7];
    const float* lin2_w    = (const float*)d_in[8];
    const float* lin2_b    = (const float*)d_in[9];
    const float* ln1_g     = (const float*)d_in[10];
    const float* ln1_bp    = (const float*)d_in[11];
    const float* ln2_g     = (const float*)d_in[12];
    const float* ln2_bp    = (const float*)d_in[13];
    const float* lnf_g     = (const float*)d_in[14];
    const float* lnf_bp    = (const float*)d_in[15];

    float *p_out, *p_qkv, *p_attn, *p_tmp, *p_h;
    unsigned char* p_kpm;
    cudaGetSymbolAddress((void**)&p_out,  g_out);
    cudaGetSymbolAddress((void**)&p_qkv,  g_qkv);
    cudaGetSymbolAddress((void**)&p_attn, g_attn);
    cudaGetSymbolAddress((void**)&p_tmp,  g_tmp);
    cudaGetSymbolAddress((void**)&p_h,    g_h);
    cudaGetSymbolAddress((void**)&p_kpm,  g_kpm);

    // key padding mask + copy x into working buffer
    kpm_kernel<<<MM, 128>>>(x, p_kpm);
    {
        int n4 = MM * DV / 4;
        copy_kernel<<<(n4 + 255) / 256, 256>>>(x, p_out, n4);
    }

    for (int l = 0; l < NLAYER; l++) {
        const float* Wq  = in_proj_w + (size_t)l * 3 * DV * DV;
        const float* bq  = in_proj_b + (size_t)l * 3 * DV;
        const float* Wo  = out_w     + (size_t)l * DV * DV;
        const float* bo  = out_b     + (size_t)l * DV;
        const float* W1  = lin1_w    + (size_t)l * DFF * DV;
        const float* b1  = lin1_b    + (size_t)l * DFF;
        const float* W2  = lin2_w    + (size_t)l * DV * DFF;
        const float* b2  = lin2_b    + (size_t)l * DV;

        // QKV projection: (8192 x 512) @ (1536 x 512)^T
        gemm_kernel<false><<<dim3(3 * DV / 128, MM / 128), 256>>>(p_out, Wq, bq, p_qkv, MM, 3 * DV, DV);
        // attention
        attn_kernel<<<dim3(BB * NH, LL / 128), 128>>>(p_qkv, dist_emb, p_kpm, p_attn);
        // output projection
        gemm_kernel<false><<<dim3(DV / 128, MM / 128), 256>>>(p_attn, Wo, bo, p_tmp, MM, DV, DV);
        // residual + LN1 (in place on p_out: each block owns its row)
        ln_kernel<<<MM, 128>>>(p_out, p_tmp, ln1_g + (size_t)l * DV, ln1_bp + (size_t)l * DV, p_out);
        // FFN
        gemm_kernel<true ><<<dim3(DFF / 128, MM / 128), 256>>>(p_out, W1, b1, p_h, MM, DFF, DV);
        gemm_kernel<false><<<dim3(DV / 128, MM / 128), 256>>>(p_h, W2, b2, p_tmp, MM, DV, DFF);
        // residual + LN2
        ln_kernel<<<MM, 128>>>(p_out, p_tmp, ln2_g + (size_t)l * DV, ln2_bp + (size_t)l * DV, p_out);
    }

    // final LayerNorm into d_out
    ln_kernel<<<MM, 128>>>(p_out, (const float*)nullptr, lnf_g, lnf_bp, (float*)d_out);
}